// round 10
// baseline (speedup 1.0000x reference)
#include <cuda_runtime.h>
#include <cstdint>

#define FD   128
#define NTHR 256
#define MAXN 50048

// ---------------- scratch (no allocations allowed) ----------------
__device__ float g_fbuf[(size_t)MAXN * FD];   // x @ W_in2fac
__device__ float g_conv[(size_t)MAXN * FD];   // segment-sum accumulator

// ---------------- smem layout (uint32 units) ----------------
// A tiles: 128 rows, 32 k per chunk, packed as uint2 (k, k+4) pairs, row pitch 36 u32
#define SA_PITCH 36
#define SA_SIZE  (128 * SA_PITCH)              // 4608 u32
// B tiles: 16 k-pair rows x 128 n (pitch 132 uint2)
#define SB_PITCH 132                            // in uint2
#define SB_SIZE  (16 * SB_PITCH * 2)            // 4224 u32
#define OFF_SAH 0
#define OFF_SAL (SA_SIZE)
#define OFF_SBH (2 * SA_SIZE)
#define OFF_SBL (2 * SA_SIZE + SB_SIZE)
#define SMEM_U32   (2 * SA_SIZE + 2 * SB_SIZE)  // 17664 u32
#define SMEM_BYTES (SMEM_U32 * 4)               // 70656 B  (sW union: 128*132*4=67584 fits)

__device__ __forceinline__ float ssp_f(float x) {
    float t = __expf(-fabsf(x));
    return fmaxf(x, 0.0f) + __logf(1.0f + t) - 0.6931471805599453f;
}
__device__ __forceinline__ uint32_t f2tf(float x) {
    uint32_t r; asm("cvt.rna.tf32.f32 %0, %1;" : "=r"(r) : "f"(x)); return r;
}
__device__ __forceinline__ void split_tf(float x, uint32_t& hi, uint32_t& lo) {
    hi = f2tf(x);
    lo = f2tf(x - __uint_as_float(hi));
}
__device__ __forceinline__ void mma8(float* d, uint32_t a0, uint32_t a1, uint32_t a2, uint32_t a3,
                                     uint32_t b0, uint32_t b1) {
    asm volatile("mma.sync.aligned.m16n8k8.row.col.f32.tf32.tf32.f32 "
                 "{%0,%1,%2,%3}, {%4,%5,%6,%7}, {%8,%9}, {%0,%1,%2,%3};"
                 : "+f"(d[0]), "+f"(d[1]), "+f"(d[2]), "+f"(d[3])
                 : "r"(a0), "r"(a1), "r"(a2), "r"(a3), "r"(b0), "r"(b1));
}

// ---------------- chunk loaders (global->regs) and stores (regs->smem, split) ----------------
__device__ __forceinline__ void ldA(float4 (&r)[4], const float* __restrict__ A,
                                    int row0, int nvalid, int kc, int tid) {
#pragma unroll
    for (int i = 0; i < 4; ++i) {
        int idx = tid + i * NTHR;          // 0..1023 float4s (128 rows x 8 float4)
        int m = idx >> 3, kq = idx & 7;
        r[i] = make_float4(0.f, 0.f, 0.f, 0.f);
        if (m < nvalid)
            r[i] = *(const float4*)(A + (size_t)(row0 + m) * FD + kc * 32 + kq * 4);
    }
}
__device__ __forceinline__ void stA(uint32_t* sAh, uint32_t* sAl, const float4 (&r)[4], int tid) {
#pragma unroll
    for (int i = 0; i < 4; ++i) {
        int idx = tid + i * NTHR;
        int m = idx >> 3, kq = idx & 7;
        const float* f = (const float*)&r[i];
#pragma unroll
        for (int j = 0; j < 4; ++j) {
            int k = kq * 4 + j;
            int ks = k >> 3, kk = k & 7;
            int o = m * SA_PITCH + ((ks * 4 + (kk & 3)) << 1) + (kk >> 2);
            uint32_t hi, lo; split_tf(f[j], hi, lo);
            sAh[o] = hi; sAl[o] = lo;
        }
    }
}
__device__ __forceinline__ void ldW(float4 (&r)[4], const float* __restrict__ W, int kc, int tid) {
#pragma unroll
    for (int i = 0; i < 4; ++i) {
        int idx = tid + i * NTHR;          // 0..1023 float4s (32 k x 32 float4)
        int k = idx >> 5, n4 = idx & 31;
        r[i] = *(const float4*)(W + (size_t)(kc * 32 + k) * FD + n4 * 4);
    }
}
__device__ __forceinline__ void stW(uint32_t* sBh, uint32_t* sBl, const float4 (&r)[4], int tid) {
#pragma unroll
    for (int i = 0; i < 4; ++i) {
        int idx = tid + i * NTHR;
        int k = idx >> 5, n4 = idx & 31;
        int ks = k >> 3, kk = k & 7;
        const float* f = (const float*)&r[i];
#pragma unroll
        for (int j = 0; j < 4; ++j) {
            int o = ((ks * 4 + (kk & 3)) * SB_PITCH + n4 * 4 + j) * 2 + (kk >> 2);
            uint32_t hi, lo; split_tf(f[j], hi, lo);
            sBh[o] = hi; sBl[o] = lo;
        }
    }
}

// ---------------- one 32-wide K chunk of mma work (3xtf32) ----------------
__device__ __forceinline__ void mma_chunk(const uint32_t* sAh, const uint32_t* sAl,
                                          const uint32_t* sBh, const uint32_t* sBl,
                                          float (&acc)[4][4][4],
                                          int mrow, int ncol0, int qr, int qc) {
#pragma unroll
    for (int ks = 0; ks < 4; ++ks) {
        uint2 ah[4][2], al[4][2];
#pragma unroll
        for (int mi = 0; mi < 4; ++mi) {
            int r0 = mrow + mi * 16 + qr;
            int o0 = r0 * SA_PITCH + ((ks * 4 + qc) << 1);
            int o1 = (r0 + 8) * SA_PITCH + ((ks * 4 + qc) << 1);
            ah[mi][0] = *(const uint2*)(sAh + o0);
            ah[mi][1] = *(const uint2*)(sAh + o1);
            al[mi][0] = *(const uint2*)(sAl + o0);
            al[mi][1] = *(const uint2*)(sAl + o1);
        }
#pragma unroll
        for (int nb = 0; nb < 4; ++nb) {
            int ob = ((ks * 4 + qc) * SB_PITCH + ncol0 + nb * 8 + qr) * 2;
            uint2 bh = *(const uint2*)(sBh + ob);
            uint2 bl = *(const uint2*)(sBl + ob);
#pragma unroll
            for (int mi = 0; mi < 4; ++mi) {
                mma8(acc[mi][nb], al[mi][0].x, al[mi][1].x, al[mi][0].y, al[mi][1].y, bh.x, bh.y);
                mma8(acc[mi][nb], ah[mi][0].x, ah[mi][1].x, ah[mi][0].y, ah[mi][1].y, bl.x, bl.y);
                mma8(acc[mi][nb], ah[mi][0].x, ah[mi][1].x, ah[mi][0].y, ah[mi][1].y, bh.x, bh.y);
            }
        }
    }
}

// ---------------- 128x128 GEMM, A from global ----------------
__device__ __forceinline__ void gemm_g(const float* __restrict__ A, int row0, int nvalid,
                                       const float* __restrict__ W,
                                       uint32_t* sm, float (&acc)[4][4][4], int tid,
                                       int mrow, int ncol0, int qr, int qc) {
    uint32_t* sAh = sm + OFF_SAH; uint32_t* sAl = sm + OFF_SAL;
    uint32_t* sBh = sm + OFF_SBH; uint32_t* sBl = sm + OFF_SBL;
    float4 rA[4], rW[4];
    ldA(rA, A, row0, nvalid, 0, tid);
    ldW(rW, W, 0, tid);
#pragma unroll
    for (int kc = 0; kc < 4; ++kc) {
        __syncthreads();
        stA(sAh, sAl, rA, tid);
        stW(sBh, sBl, rW, tid);
        if (kc < 3) { ldA(rA, A, row0, nvalid, kc + 1, tid); ldW(rW, W, kc + 1, tid); }
        __syncthreads();
        mma_chunk(sAh, sAl, sBh, sBl, acc, mrow, ncol0, qr, qc);
    }
}

// ---------------- 128x128 GEMM, A = h held in C-fragments across warps ----------------
__device__ __forceinline__ void gemm_c(const float (&h)[4][4][4], const float* __restrict__ W,
                                       uint32_t* sm, float (&acc)[4][4][4], int tid,
                                       int wid, int mrow, int ncol0, int qr, int qc) {
    uint32_t* sAh = sm + OFF_SAH; uint32_t* sAl = sm + OFF_SAL;
    uint32_t* sBh = sm + OFF_SBH; uint32_t* sBl = sm + OFF_SBL;
    float4 rW[4];
    ldW(rW, W, 0, tid);
#pragma unroll
    for (int kc = 0; kc < 4; ++kc) {
        __syncthreads();
        if ((wid & 3) == kc) {   // this warp's h columns are this chunk's k range
#pragma unroll
            for (int mi = 0; mi < 4; ++mi)
#pragma unroll
                for (int nb = 0; nb < 4; ++nb)
#pragma unroll
                    for (int r = 0; r < 4; ++r) {
                        int row = mrow + mi * 16 + qr + (r >> 1) * 8;
                        int kk = 2 * qc + (r & 1);          // ks = nb
                        int o = row * SA_PITCH + ((nb * 4 + (kk & 3)) << 1) + (kk >> 2);
                        uint32_t hi, lo; split_tf(h[mi][nb][r], hi, lo);
                        sAh[o] = hi; sAl[o] = lo;
                    }
        }
        stW(sBh, sBl, rW, tid);
        if (kc < 3) ldW(rW, W, kc + 1, tid);
        __syncthreads();
        mma_chunk(sAh, sAl, sBh, sBl, acc, mrow, ncol0, qr, qc);
    }
}

__device__ __forceinline__ void bias_ssp(float (&a)[4][4][4], const float* __restrict__ b,
                                         int ncol0, int qc) {
#pragma unroll
    for (int nb = 0; nb < 4; ++nb) {
        float2 bb = *(const float2*)(b + ncol0 + nb * 8 + 2 * qc);
#pragma unroll
        for (int mi = 0; mi < 4; ++mi) {
            a[mi][nb][0] = ssp_f(a[mi][nb][0] + bb.x);
            a[mi][nb][1] = ssp_f(a[mi][nb][1] + bb.y);
            a[mi][nb][2] = ssp_f(a[mi][nb][2] + bb.x);
            a[mi][nb][3] = ssp_f(a[mi][nb][3] + bb.y);
        }
    }
}

// ---------------- kernels ----------------
__global__ void k_zero(int n4) {
    int i = blockIdx.x * blockDim.x + threadIdx.x;
    if (i < n4) ((float4*)g_conv)[i] = make_float4(0.f, 0.f, 0.f, 0.f);
}

__global__ void __launch_bounds__(NTHR, 1) k_in2fac(const float* __restrict__ x,
                                                    const float* __restrict__ Wi, int N) {
    extern __shared__ uint32_t sm[];
    int tid = threadIdx.x, lane = tid & 31, wid = tid >> 5;
    int qr = lane >> 2, qc = lane & 3;
    int mrow = (wid >> 2) * 64, ncol0 = (wid & 3) * 32;
    int row0 = blockIdx.x * 128;
    int nv = min(128, N - row0);

    float acc[4][4][4] = {};
    gemm_g(x, row0, nv, Wi, sm, acc, tid, mrow, ncol0, qr, qc);

#pragma unroll
    for (int mi = 0; mi < 4; ++mi)
#pragma unroll
        for (int rh = 0; rh < 2; ++rh) {
            int row = row0 + mrow + mi * 16 + qr + rh * 8;
            if (row < N) {
#pragma unroll
                for (int nb = 0; nb < 4; ++nb)
                    *(float2*)(g_fbuf + (size_t)row * FD + ncol0 + nb * 8 + 2 * qc) =
                        make_float2(acc[mi][nb][rh * 2], acc[mi][nb][rh * 2 + 1]);
            }
        }
}

__global__ void __launch_bounds__(NTHR, 1) k_edge(const float* __restrict__ dijk,
                                                  const float* __restrict__ W1,
                                                  const float* __restrict__ b1,
                                                  const float* __restrict__ W2,
                                                  const float* __restrict__ b2,
                                                  const int* __restrict__ idx_j,
                                                  const int* __restrict__ seg_i, int E) {
    extern __shared__ uint32_t sm[];
    int tid = threadIdx.x, lane = tid & 31, wid = tid >> 5;
    int qr = lane >> 2, qc = lane & 3;
    int mrow = (wid >> 2) * 64, ncol0 = (wid & 3) * 32;
    int e0 = blockIdx.x * 128;
    int nv = min(128, E - e0);

    // h = ssp(dijk @ W1 + b1)
    float h[4][4][4] = {};
    gemm_g(dijk, e0, nv, W1, sm, h, tid, mrow, ncol0, qr, qc);
    bias_ssp(h, b1, ncol0, qc);

    // w = ssp(h @ W2 + b2)   (seg_j == arange -> first segment_sum is identity)
    float w[4][4][4] = {};
    gemm_c(h, W2, sm, w, tid, wid, mrow, ncol0, qr, qc);
    bias_ssp(w, b2, ncol0, qc);

    // stage w tile to smem (union buffer), then row-major epilogue
    __syncthreads();
    float* sW = (float*)sm;    // pitch 132 floats, 128 rows
#pragma unroll
    for (int mi = 0; mi < 4; ++mi)
#pragma unroll
        for (int rh = 0; rh < 2; ++rh) {
            int row = mrow + mi * 16 + qr + rh * 8;
#pragma unroll
            for (int nb = 0; nb < 4; ++nb)
                *(float2*)(sW + row * 132 + ncol0 + nb * 8 + 2 * qc) =
                    make_float2(w[mi][nb][rh * 2], w[mi][nb][rh * 2 + 1]);
        }
    __syncthreads();

    // wf = w * f[idx_j]; run-length-compressed segmented atomicAdd into g_conv[seg_i]
    int tx = tid & 15, ty = tid >> 4;
    int col0 = tx * 8;
    float accv[8];
    int cur = -1;
#pragma unroll
    for (int r = 0; r < 8; ++r) {
        int e = e0 + ty * 8 + r;
        if (e < E) {
            int j = idx_j[e];
            const float4* frow = (const float4*)(g_fbuf + (size_t)j * FD + col0);
            float4 f0 = frow[0], f1 = frow[1];
            const float* wr = sW + (ty * 8 + r) * 132 + col0;
            float4 w0 = *(const float4*)(wr);
            float4 w1 = *(const float4*)(wr + 4);
            float wf[8] = { w0.x * f0.x, w0.y * f0.y, w0.z * f0.z, w0.w * f0.w,
                            w1.x * f1.x, w1.y * f1.y, w1.z * f1.z, w1.w * f1.w };
            int s = seg_i[e];
            if (s != cur) {
                if (cur >= 0) {
                    float* dst = g_conv + (size_t)cur * FD + col0;
#pragma unroll
                    for (int c = 0; c < 8; ++c) atomicAdd(dst + c, accv[c]);
                }
                cur = s;
#pragma unroll
                for (int c = 0; c < 8; ++c) accv[c] = wf[c];
            } else {
#pragma unroll
                for (int c = 0; c < 8; ++c) accv[c] += wf[c];
            }
        }
    }
    if (cur >= 0) {
        float* dst = g_conv + (size_t)cur * FD + col0;
#pragma unroll
        for (int c = 0; c < 8; ++c) atomicAdd(dst + c, accv[c]);
    }
}

__global__ void __launch_bounds__(NTHR, 1) k_atom(const float* __restrict__ x,
                                                  const float* __restrict__ Wf,
                                                  const float* __restrict__ bf,
                                                  const float* __restrict__ Wd,
                                                  const float* __restrict__ bd,
                                                  float* __restrict__ out,
                                                  int N, int hasv) {
    extern __shared__ uint32_t sm[];
    int tid = threadIdx.x, lane = tid & 31, wid = tid >> 5;
    int qr = lane >> 2, qc = lane & 3;
    int mrow = (wid >> 2) * 64, ncol0 = (wid & 3) * 32;
    int row0 = blockIdx.x * 128;
    int nv = min(128, N - row0);

    // c = ssp(conv @ W_fac2out + b_fac2out)
    float h[4][4][4] = {};
    gemm_g((const float*)g_conv, row0, nv, Wf, sm, h, tid, mrow, ncol0, qr, qc);
    bias_ssp(h, bf, ncol0, qc);

    // v = c @ W_dense + b_dense;  y = x + v
    float v[4][4][4] = {};
    gemm_c(h, Wd, sm, v, tid, wid, mrow, ncol0, qr, qc);

#pragma unroll
    for (int mi = 0; mi < 4; ++mi)
#pragma unroll
        for (int rh = 0; rh < 2; ++rh) {
            int row = row0 + mrow + mi * 16 + qr + rh * 8;
            if (row < N) {
#pragma unroll
                for (int nb = 0; nb < 4; ++nb) {
                    int col = ncol0 + nb * 8 + 2 * qc;
                    float2 bb = *(const float2*)(bd + col);
                    float2 xv = *(const float2*)(x + (size_t)row * FD + col);
                    float2 vv = make_float2(v[mi][nb][rh * 2] + bb.x,
                                            v[mi][nb][rh * 2 + 1] + bb.y);
                    *(float2*)(out + (size_t)row * FD + col) =
                        make_float2(xv.x + vv.x, xv.y + vv.y);
                    if (hasv)
                        *(float2*)(out + (size_t)N * FD + (size_t)row * FD + col) = vv;
                }
            }
        }
}

extern "C" void kernel_launch(void* const* d_in, const int* in_sizes, int n_in,
                              void* d_out, int out_size) {
    const float* x    = (const float*)d_in[0];
    const float* dijk = (const float*)d_in[1];
    const int* idx_j  = (const int*)d_in[2];
    const int* seg_i  = (const int*)d_in[3];
    int wb = 4;
    while (wb < n_in && in_sizes[wb] != FD * FD) ++wb;
    const float* W1 = (const float*)d_in[wb + 0];
    const float* b1 = (const float*)d_in[wb + 1];
    const float* W2 = (const float*)d_in[wb + 2];
    const float* b2 = (const float*)d_in[wb + 3];
    const float* Wi = (const float*)d_in[wb + 4];
    const float* Wf = (const float*)d_in[wb + 5];
    const float* bf = (const float*)d_in[wb + 6];
    const float* Wd = (const float*)d_in[wb + 7];
    const float* bd = (const float*)d_in[wb + 8];

    int N = in_sizes[0] / FD;
    int E = in_sizes[1] / FD;
    float* out = (float*)d_out;
    int hasv = (out_size >= 2 * N * FD) ? 1 : 0;

    // opt-in to >48KB dynamic smem (idempotent, not a stream op; capture-safe)
    cudaFuncSetAttribute(k_in2fac, cudaFuncAttributeMaxDynamicSharedMemorySize, SMEM_BYTES);
    cudaFuncSetAttribute(k_edge,   cudaFuncAttributeMaxDynamicSharedMemorySize, SMEM_BYTES);
    cudaFuncSetAttribute(k_atom,   cudaFuncAttributeMaxDynamicSharedMemorySize, SMEM_BYTES);

    int nblkN = (N + 127) / 128;
    int nblkE = (E + 127) / 128;
    int n4 = (N * FD) / 4;

    k_zero<<<(n4 + 255) / 256, 256>>>(n4);
    k_in2fac<<<nblkN, NTHR, SMEM_BYTES>>>(x, Wi, N);
    k_edge<<<nblkE, NTHR, SMEM_BYTES>>>(dijk, W1, b1, W2, b2, idx_j, seg_i, E);
    k_atom<<<nblkN, NTHR, SMEM_BYTES>>>(x, Wf, bf, Wd, bd, out, N, hasv);
}

// round 11
// speedup vs baseline: 2.9474x; 2.9474x over previous
#include <cuda_runtime.h>
#include <cuda_bf16.h>
#include <cstdint>

#define FD   128
#define NTHR 512
#define MAXN 50048

// ---------------- scratch (no allocations allowed) ----------------
__device__ float g_fbuf[(size_t)MAXN * FD];   // x @ W_in2fac
__device__ float g_conv[(size_t)MAXN * FD];   // segment-sum accumulator

// ---------------- smem layout (uint32 units) ----------------
// chunk-A: 128 rows x 16 k-pair u32, pitch 18; hi then lo
#define ACP 18
#define OFF_ACH 0
#define OFF_ACL 2304
// B: 8 rowslots (s*4+qc) x pitch 136; four arrays: half0-hi, half0-lo, half1-hi, half1-lo
#define BNP 136
#define OFF_B0H 4608
#define OFF_B0L (4608 + 1088)
#define OFF_B1H (4608 + 2176)
#define OFF_B1L (4608 + 3264)
// full-A (staged h, all K=128): 128 rows x 64 k-pair u32, pitch 68; hi then lo
#define FAP 68
#define OFF_FAH 8960
#define OFF_FAL (8960 + 8704)
#define SMEM_U32   (8960 + 17408)
#define SMEM_BYTES (SMEM_U32 * 4)        // 105472 B

__device__ __forceinline__ float ssp_f(float x) {
    float t = __expf(-fabsf(x));
    return fmaxf(x, 0.0f) + __logf(1.0f + t) - 0.6931471805599453f;
}

// pack two consecutive-k floats into bf16x2 hi and residual-lo words
__device__ __forceinline__ void split2(float x0, float x1, uint32_t& hi, uint32_t& lo) {
    __nv_bfloat162 h = __floats2bfloat162_rn(x0, x1);     // .x = x0 (low half)
    float r0 = x0 - __bfloat162float(h.x);
    float r1 = x1 - __bfloat162float(h.y);
    __nv_bfloat162 l = __floats2bfloat162_rn(r0, r1);
    hi = *reinterpret_cast<uint32_t*>(&h);
    lo = *reinterpret_cast<uint32_t*>(&l);
}

__device__ __forceinline__ void mma16(float* d, uint32_t a0, uint32_t a1, uint32_t a2, uint32_t a3,
                                      uint32_t b0, uint32_t b1) {
    asm volatile("mma.sync.aligned.m16n8k16.row.col.f32.bf16.bf16.f32 "
                 "{%0,%1,%2,%3}, {%4,%5,%6,%7}, {%8,%9}, {%0,%1,%2,%3};"
                 : "+f"(d[0]), "+f"(d[1]), "+f"(d[2]), "+f"(d[3])
                 : "r"(a0), "r"(a1), "r"(a2), "r"(a3), "r"(b0), "r"(b1));
}

// ---------------- chunk loaders / smem stores ----------------
__device__ __forceinline__ void ldA(float4 (&r)[2], const float* __restrict__ A,
                                    int row0, int nv, int kc, int tid) {
#pragma unroll
    for (int i = 0; i < 2; ++i) {
        int idx = tid + i * NTHR;         // 0..1023 float4 = 128 rows x 8
        int m = idx >> 3, kq = idx & 7;
        r[i] = make_float4(0.f, 0.f, 0.f, 0.f);
        if (m < nv) r[i] = *(const float4*)(A + (size_t)(row0 + m) * FD + kc * 32 + kq * 4);
    }
}
__device__ __forceinline__ void stA(uint32_t* sm, const float4 (&r)[2], int tid) {
#pragma unroll
    for (int i = 0; i < 2; ++i) {
        int idx = tid + i * NTHR;
        int m = idx >> 3, kq = idx & 7;
        const float* f = (const float*)&r[i];
#pragma unroll
        for (int j2 = 0; j2 < 2; ++j2) {
            int p = kq * 2 + j2;                       // k-pair 0..15
            int s = p >> 3, q = p & 7;
            int col = s * 8 + (q & 3) * 2 + (q >> 2);  // perm so frags are uint2
            uint32_t hi, lo; split2(f[2 * j2], f[2 * j2 + 1], hi, lo);
            sm[OFF_ACH + m * ACP + col] = hi;
            sm[OFF_ACL + m * ACP + col] = lo;
        }
    }
}
__device__ __forceinline__ void ldW(float (&fa)[4], float (&fb)[4],
                                    const float* __restrict__ W, int kc, int tid) {
    int p = tid >> 5, n0 = tid & 31;                   // p = k-pair, lanes span n
    const float* r0 = W + (size_t)(kc * 32 + 2 * p) * FD + n0;
#pragma unroll
    for (int j = 0; j < 4; ++j) { fa[j] = r0[32 * j]; fb[j] = r0[FD + 32 * j]; }
}
__device__ __forceinline__ void stW(uint32_t* sm, const float (&fa)[4], const float (&fb)[4], int tid) {
    int p = tid >> 5, n0 = tid & 31;
    int s = p >> 3, q = p & 7;
    int base = (s * 4 + (q & 3)) * BNP + n0;
    int oh = (q >> 2) ? OFF_B1H : OFF_B0H;
    int ol = (q >> 2) ? OFF_B1L : OFF_B0L;
#pragma unroll
    for (int j = 0; j < 4; ++j) {
        uint32_t hi, lo; split2(fa[j], fb[j], hi, lo);
        sm[oh + base + 32 * j] = hi;
        sm[ol + base + 32 * j] = lo;
    }
}

// ---------------- 32-wide K chunk of mma (3x bf16) ----------------
__device__ __forceinline__ void mma_chunk(const uint32_t* sm, int aoffH, int aoffL, int apitch, int acol,
                                          float (&acc)[2][4][4], int mrow, int ncol0, int qr, int qc) {
#pragma unroll
    for (int s = 0; s < 2; ++s) {
        uint2 Ah[2][2], Al[2][2];
#pragma unroll
        for (int mi = 0; mi < 2; ++mi) {
            int r0 = mrow + mi * 16 + qr;
            int c = acol + s * 8 + qc * 2;
            Ah[mi][0] = *(const uint2*)(sm + aoffH + r0 * apitch + c);
            Ah[mi][1] = *(const uint2*)(sm + aoffH + (r0 + 8) * apitch + c);
            Al[mi][0] = *(const uint2*)(sm + aoffL + r0 * apitch + c);
            Al[mi][1] = *(const uint2*)(sm + aoffL + (r0 + 8) * apitch + c);
        }
        int bbase = (s * 4 + qc) * BNP + ncol0 + qr;
#pragma unroll
        for (int nb = 0; nb < 4; ++nb) {
            uint32_t b0h = sm[OFF_B0H + bbase + nb * 8];
            uint32_t b1h = sm[OFF_B1H + bbase + nb * 8];
            uint32_t b0l = sm[OFF_B0L + bbase + nb * 8];
            uint32_t b1l = sm[OFF_B1L + bbase + nb * 8];
#pragma unroll
            for (int mi = 0; mi < 2; ++mi) {
                mma16(acc[mi][nb], Ah[mi][0].x, Ah[mi][1].x, Ah[mi][0].y, Ah[mi][1].y, b0l, b1l);
                mma16(acc[mi][nb], Al[mi][0].x, Al[mi][1].x, Al[mi][0].y, Al[mi][1].y, b0h, b1h);
                mma16(acc[mi][nb], Ah[mi][0].x, Ah[mi][1].x, Ah[mi][0].y, Ah[mi][1].y, b0h, b1h);
            }
        }
    }
}

// ---------------- 128x128x128 GEMM, A from global ----------------
__device__ __forceinline__ void gemm_g(const float* __restrict__ A, int row0, int nv,
                                       const float* __restrict__ W,
                                       uint32_t* sm, float (&acc)[2][4][4], int tid,
                                       int mrow, int ncol0, int qr, int qc) {
    float4 rA[2]; float fa[4], fb[4];
    ldA(rA, A, row0, nv, 0, tid);
    ldW(fa, fb, W, 0, tid);
#pragma unroll
    for (int kc = 0; kc < 4; ++kc) {
        __syncthreads();
        stA(sm, rA, tid);
        stW(sm, fa, fb, tid);
        if (kc < 3) { ldA(rA, A, row0, nv, kc + 1, tid); ldW(fa, fb, W, kc + 1, tid); }
        __syncthreads();
        mma_chunk(sm, OFF_ACH, OFF_ACL, ACP, 0, acc, mrow, ncol0, qr, qc);
    }
}

// stage h fragments (post-ssp) into resident full-A smem, split bf16 hi/lo
__device__ __forceinline__ void stage_h(uint32_t* sm, const float (&h)[2][4][4],
                                        int wid_n, int mrow, int qr, int qc) {
#pragma unroll
    for (int mi = 0; mi < 2; ++mi)
#pragma unroll
        for (int nb = 0; nb < 4; ++nb) {
            int col = wid_n * 16 + (nb >> 1) * 8 + qc * 2 + (nb & 1);
            int rlo = mrow + mi * 16 + qr;
            uint32_t hi, lo;
            split2(h[mi][nb][0], h[mi][nb][1], hi, lo);
            sm[OFF_FAH + rlo * FAP + col] = hi;
            sm[OFF_FAL + rlo * FAP + col] = lo;
            split2(h[mi][nb][2], h[mi][nb][3], hi, lo);
            sm[OFF_FAH + (rlo + 8) * FAP + col] = hi;
            sm[OFF_FAL + (rlo + 8) * FAP + col] = lo;
        }
}

// second GEMM: A resident in full-A smem, only W restaged per chunk
__device__ __forceinline__ void gemm_c(const float* __restrict__ W, uint32_t* sm,
                                       float (&acc)[2][4][4], int tid,
                                       int mrow, int ncol0, int qr, int qc) {
    float fa[4], fb[4];
    ldW(fa, fb, W, 0, tid);
#pragma unroll
    for (int kc = 0; kc < 4; ++kc) {
        __syncthreads();          // (kc==0 also orders stage_h writes)
        stW(sm, fa, fb, tid);
        if (kc < 3) ldW(fa, fb, W, kc + 1, tid);
        __syncthreads();
        mma_chunk(sm, OFF_FAH, OFF_FAL, FAP, kc * 16, acc, mrow, ncol0, qr, qc);
    }
}

__device__ __forceinline__ void bias_ssp(float (&a)[2][4][4], const float* __restrict__ b,
                                         int ncol0, int qc) {
#pragma unroll
    for (int nb = 0; nb < 4; ++nb) {
        float2 bb = *(const float2*)(b + ncol0 + nb * 8 + 2 * qc);
#pragma unroll
        for (int mi = 0; mi < 2; ++mi) {
            a[mi][nb][0] = ssp_f(a[mi][nb][0] + bb.x);
            a[mi][nb][1] = ssp_f(a[mi][nb][1] + bb.y);
            a[mi][nb][2] = ssp_f(a[mi][nb][2] + bb.x);
            a[mi][nb][3] = ssp_f(a[mi][nb][3] + bb.y);
        }
    }
}

// ---------------- kernels ----------------
__global__ void k_zero(int n4) {
    int i = blockIdx.x * blockDim.x + threadIdx.x;
    if (i < n4) ((float4*)g_conv)[i] = make_float4(0.f, 0.f, 0.f, 0.f);
}

__global__ void __launch_bounds__(NTHR, 1) k_in2fac(const float* __restrict__ x,
                                                    const float* __restrict__ Wi, int N) {
    extern __shared__ uint32_t sm[];
    int tid = threadIdx.x, lane = tid & 31, wid = tid >> 5;
    int qr = lane >> 2, qc = lane & 3;
    int mrow = (wid >> 2) * 32, ncol0 = (wid & 3) * 32;
    int row0 = blockIdx.x * 128;
    int nv = min(128, N - row0);

    float acc[2][4][4] = {};
    gemm_g(x, row0, nv, Wi, sm, acc, tid, mrow, ncol0, qr, qc);

#pragma unroll
    for (int mi = 0; mi < 2; ++mi)
#pragma unroll
        for (int rh = 0; rh < 2; ++rh) {
            int row = row0 + mrow + mi * 16 + qr + rh * 8;
            if (row < N) {
#pragma unroll
                for (int nb = 0; nb < 4; ++nb)
                    *(float2*)(g_fbuf + (size_t)row * FD + ncol0 + nb * 8 + 2 * qc) =
                        make_float2(acc[mi][nb][rh * 2], acc[mi][nb][rh * 2 + 1]);
            }
        }
}

__global__ void __launch_bounds__(NTHR, 1) k_edge(const float* __restrict__ dijk,
                                                  const float* __restrict__ W1,
                                                  const float* __restrict__ b1,
                                                  const float* __restrict__ W2,
                                                  const float* __restrict__ b2,
                                                  const int* __restrict__ idx_j,
                                                  const int* __restrict__ seg_i, int E) {
    extern __shared__ uint32_t sm[];
    int tid = threadIdx.x, lane = tid & 31, wid = tid >> 5;
    int qr = lane >> 2, qc = lane & 3;
    int mrow = (wid >> 2) * 32, ncol0 = (wid & 3) * 32;
    int e0 = blockIdx.x * 128;
    int nv = min(128, E - e0);

    // h = ssp(dijk @ W1 + b1)
    float h[2][4][4] = {};
    gemm_g(dijk, e0, nv, W1, sm, h, tid, mrow, ncol0, qr, qc);
    bias_ssp(h, b1, ncol0, qc);
    stage_h(sm, h, wid & 3, mrow, qr, qc);   // h -> resident split A (disjoint smem region)

    // w = ssp(h @ W2 + b2)  (seg_j == arange -> first segment_sum is identity)
    float w[2][4][4] = {};
    gemm_c(W2, sm, w, tid, mrow, ncol0, qr, qc);
    bias_ssp(w, b2, ncol0, qc);

    // stage w tile to fp32 smem (reuse everything), then RLE epilogue
    __syncthreads();
    float* sW = (float*)sm;                  // 128 rows x pitch 132
#pragma unroll
    for (int mi = 0; mi < 2; ++mi)
#pragma unroll
        for (int rh = 0; rh < 2; ++rh) {
            int row = mrow + mi * 16 + qr + rh * 8;
#pragma unroll
            for (int nb = 0; nb < 4; ++nb)
                *(float2*)(sW + row * 132 + ncol0 + nb * 8 + 2 * qc) =
                    make_float2(w[mi][nb][rh * 2], w[mi][nb][rh * 2 + 1]);
        }
    __syncthreads();

    // wf = w * f[idx_j]; run-length-compressed segmented atomicAdd into g_conv[seg_i]
    int tx = tid & 31, ty = tid >> 5;        // 32 col-groups of 4, 16 row-groups of 8
    int col0 = tx * 4;
    float accv[4];
    int cur = -1;
#pragma unroll
    for (int r = 0; r < 8; ++r) {
        int lr = ty * 8 + r;
        int e = e0 + lr;
        if (e < E) {
            int j = idx_j[e];
            float4 f0 = *(const float4*)(g_fbuf + (size_t)j * FD + col0);
            float4 w0 = *(const float4*)(sW + lr * 132 + col0);
            float wf[4] = { w0.x * f0.x, w0.y * f0.y, w0.z * f0.z, w0.w * f0.w };
            int s = seg_i[e];
            if (s != cur) {
                if (cur >= 0) {
                    float* dst = g_conv + (size_t)cur * FD + col0;
#pragma unroll
                    for (int c = 0; c < 4; ++c) atomicAdd(dst + c, accv[c]);
                }
                cur = s;
#pragma unroll
                for (int c = 0; c < 4; ++c) accv[c] = wf[c];
            } else {
#pragma unroll
                for (int c = 0; c < 4; ++c) accv[c] += wf[c];
            }
        }
    }
    if (cur >= 0) {
        float* dst = g_conv + (size_t)cur * FD + col0;
#pragma unroll
        for (int c = 0; c < 4; ++c) atomicAdd(dst + c, accv[c]);
    }
}

__global__ void __launch_bounds__(NTHR, 1) k_atom(const float* __restrict__ x,
                                                  const float* __restrict__ Wf,
                                                  const float* __restrict__ bf,
                                                  const float* __restrict__ Wd,
                                                  const float* __restrict__ bd,
                                                  float* __restrict__ out,
                                                  int N, int hasv) {
    extern __shared__ uint32_t sm[];
    int tid = threadIdx.x, lane = tid & 31, wid = tid >> 5;
    int qr = lane >> 2, qc = lane & 3;
    int mrow = (wid >> 2) * 32, ncol0 = (wid & 3) * 32;
    int row0 = blockIdx.x * 128;
    int nv = min(128, N - row0);

    // c = ssp(conv @ W_fac2out + b_fac2out)
    float h[2][4][4] = {};
    gemm_g((const float*)g_conv, row0, nv, Wf, sm, h, tid, mrow, ncol0, qr, qc);
    bias_ssp(h, bf, ncol0, qc);
    stage_h(sm, h, wid & 3, mrow, qr, qc);

    // v = c @ W_dense + b_dense; y = x + v
    float v[2][4][4] = {};
    gemm_c(Wd, sm, v, tid, mrow, ncol0, qr, qc);

#pragma unroll
    for (int mi = 0; mi < 2; ++mi)
#pragma unroll
        for (int rh = 0; rh < 2; ++rh) {
            int row = row0 + mrow + mi * 16 + qr + rh * 8;
            if (row < N) {
#pragma unroll
                for (int nb = 0; nb < 4; ++nb) {
                    int col = ncol0 + nb * 8 + 2 * qc;
                    float2 bb = *(const float2*)(bd + col);
                    float2 xv = *(const float2*)(x + (size_t)row * FD + col);
                    float2 vv = make_float2(v[mi][nb][rh * 2] + bb.x,
                                            v[mi][nb][rh * 2 + 1] + bb.y);
                    *(float2*)(out + (size_t)row * FD + col) =
                        make_float2(xv.x + vv.x, xv.y + vv.y);
                    if (hasv)
                        *(float2*)(out + (size_t)N * FD + (size_t)row * FD + col) = vv;
                }
            }
        }
}

extern "C" void kernel_launch(void* const* d_in, const int* in_sizes, int n_in,
                              void* d_out, int out_size) {
    const float* x    = (const float*)d_in[0];
    const float* dijk = (const float*)d_in[1];
    const int* idx_j  = (const int*)d_in[2];
    const int* seg_i  = (const int*)d_in[3];
    int wb = 4;
    while (wb < n_in && in_sizes[wb] != FD * FD) ++wb;
    const float* W1 = (const float*)d_in[wb + 0];
    const float* b1 = (const float*)d_in[wb + 1];
    const float* W2 = (const float*)d_in[wb + 2];
    const float* b2 = (const float*)d_in[wb + 3];
    const float* Wi = (const float*)d_in[wb + 4];
    const float* Wf = (const float*)d_in[wb + 5];
    const float* bf = (const float*)d_in[wb + 6];
    const float* Wd = (const float*)d_in[wb + 7];
    const float* bd = (const float*)d_in[wb + 8];

    int N = in_sizes[0] / FD;
    int E = in_sizes[1] / FD;
    float* out = (float*)d_out;
    int hasv = (out_size >= 2 * N * FD) ? 1 : 0;

    cudaFuncSetAttribute(k_in2fac, cudaFuncAttributeMaxDynamicSharedMemorySize, SMEM_BYTES);
    cudaFuncSetAttribute(k_edge,   cudaFuncAttributeMaxDynamicSharedMemorySize, SMEM_BYTES);
    cudaFuncSetAttribute(k_atom,   cudaFuncAttributeMaxDynamicSharedMemorySize, SMEM_BYTES);

    int nblkN = (N + 127) / 128;
    int nblkE = (E + 127) / 128;
    int n4 = (N * FD) / 4;

    k_zero<<<(n4 + 255) / 256, 256>>>(n4);
    k_in2fac<<<nblkN, NTHR, SMEM_BYTES>>>(x, Wi, N);
    k_edge<<<nblkE, NTHR, SMEM_BYTES>>>(dijk, W1, b1, W2, b2, idx_j, seg_i, E);
    k_atom<<<nblkN, NTHR, SMEM_BYTES>>>(x, Wf, bf, Wd, bd, out, N, hasv);
}